// round 7
// baseline (speedup 1.0000x reference)
#include <cuda_runtime.h>
#include <stdint.h>

typedef unsigned int u32;
typedef unsigned long long u64;
typedef uint8_t u8;

// Ping-pong activation scratch: 16 imgs * 512*512 pixels * up to 16 ch (NHWC)
__device__ __align__(16) u8 g_bufA[(size_t)16 * 512 * 512 * 16];
__device__ __align__(16) u8 g_bufB[(size_t)16 * 512 * 512 * 16];

__device__ __forceinline__ int dp4a_us(u32 a, int b, int c) {
    int d;
    asm("dp4a.u32.s32 %0, %1, %2, %3;" : "=r"(d) : "r"(a), "r"(b), "r"(c));
    return d;
}
__device__ __forceinline__ int dp4a_ss(int a, int b, int c) {
    int d;
    asm("dp4a.s32.s32 %0, %1, %2, %3;" : "=r"(d) : "r"(a), "r"(b), "r"(c));
    return d;
}
__device__ __forceinline__ u64 fma2(u64 a, u64 b, u64 c) {
    u64 d;
    asm("fma.rn.f32x2 %0, %1, %2, %3;" : "=l"(d) : "l"(a), "l"(b), "l"(c));
    return d;
}
__device__ __forceinline__ u64 pack2(float lo, float hi) {
    u64 d;
    asm("mov.b64 %0, {%1, %2};" : "=l"(d) : "f"(lo), "f"(hi));
    return d;
}

// requant: clip(round(acc*M),-127,127) then relu == rni+sat-to-u8 after min 127
__device__ __forceinline__ u32 requant_u8(int acc, float M) {
    float f = fminf((float)acc * M, 127.0f);
    unsigned short s;
    asm("cvt.rni.sat.u8.f32 %0, %1;" : "=h"(s) : "f"(f));
    return (u32)s;
}
// insert byte q.b0 into byte lane k of go (k=1,2,3); k=0 is plain assign
__device__ __forceinline__ u32 bins(u32 go, u32 q, int k) {
    const u32 sel[4] = {0x3214u, 0x3240u, 0x3410u, 0x4210u};
    return __byte_perm(go, q, sel[k]);
}

// ---------------------------------------------------------------------------
// Front: quantize + layer0 (5x5, 1->16, pad 2) + layer1 (1x1, 16->12) fused.
// in: x float, out: g_bufB NHWC12
// ---------------------------------------------------------------------------
__global__ __launch_bounds__(256) void k_front(const float* __restrict__ x,
                                               const int* __restrict__ w0,
                                               const int* __restrict__ b0,
                                               const int* __restrict__ w1,
                                               const int* __restrict__ b1,
                                               float M0, float M1) {
    __shared__ __align__(16) u8 tile[12][36];
    __shared__ __align__(16) int4 sw[16][2];
    __shared__ int4 sw1[12];
    __shared__ int sb1[12];
    int tx = threadIdx.x, ty = threadIdx.y;
    int tid = ty * 32 + tx;
    int bx = blockIdx.x * 32, by = blockIdx.y * 8, n = blockIdx.z;
    size_t ibase = (size_t)n * 262144;
    const float inv_s = (float)(1.0 / 255.0);

    for (int i = tid; i < 432; i += 256) {
        int r = i / 36, c = i % 36;
        int gy = by - 2 + r, gx = bx - 2 + c;
        u8 v = 0;
        if ((unsigned)gy < 512u && (unsigned)gx < 512u) {
            float f = x[ibase + (size_t)gy * 512 + gx];
            v = (u8)min(max(__float2int_rn(f / inv_s), 0), 255);
        }
        tile[r][c] = v;
    }
    if (tid < 16) {
        int oc = tid;
        int rw[5];
        int cw = 0;
#pragma unroll
        for (int ky = 0; ky < 5; ky++) {
            int wv = 0;
#pragma unroll
            for (int kx = 0; kx < 4; kx++)
                wv |= ((w0[oc * 25 + ky * 5 + kx] - 128) & 255) << (8 * kx);
            rw[ky] = wv;
        }
#pragma unroll
        for (int ky = 0; ky < 4; ky++)
            cw |= ((w0[oc * 25 + ky * 5 + 4] - 128) & 255) << (8 * ky);
        int corner = w0[oc * 25 + 24] - 128;
        sw[oc][0] = make_int4(rw[0], rw[1], rw[2], rw[3]);
        sw[oc][1] = make_int4(rw[4], cw, corner, b0[oc]);
    }
    if (tid >= 32 && tid < 44) {
        int oc = tid - 32;
        int ww[4];
#pragma unroll
        for (int g = 0; g < 4; g++) {
            int v = 0;
#pragma unroll
            for (int j = 0; j < 4; j++)
                v |= ((w1[oc * 16 + 4 * g + j] - 128) & 255) << (8 * j);
            ww[g] = v;
        }
        sw1[oc] = make_int4(ww[0], ww[1], ww[2], ww[3]);
        sb1[oc] = b1[oc];
    }
    __syncthreads();

    u32 r[5], colw = 0;
    int corner_v = 0;
    int s = (tx & 3) * 8;
#pragma unroll
    for (int k = 0; k < 5; k++) {
        const u32* rowp = (const u32*)&tile[ty + k][0];
        u32 wlo = rowp[tx >> 2], whi = rowp[(tx >> 2) + 1];
        r[k] = __funnelshift_r(wlo, whi, s);
        u32 b4 = (whi >> s) & 255u;
        if (k < 4) colw |= b4 << (8 * k); else corner_v = (int)b4;
    }

    u32 a16[4] = {0, 0, 0, 0};
#pragma unroll
    for (int oc = 0; oc < 16; oc++) {
        int4 qa = sw[oc][0];
        int4 qb = sw[oc][1];
        int acc = qb.w;
        acc = dp4a_us(r[0], qa.x, acc);
        acc = dp4a_us(r[1], qa.y, acc);
        acc = dp4a_us(r[2], qa.z, acc);
        acc = dp4a_us(r[3], qa.w, acc);
        acc = dp4a_us(r[4], qb.x, acc);
        acc = dp4a_us(colw, qb.y, acc);
        acc += corner_v * qb.z;
        u32 q = requant_u8(acc, M0);
        int k = oc & 3;
        a16[oc >> 2] = (k == 0) ? q : bins(a16[oc >> 2], q, k);
    }

    u32 ow[3] = {0, 0, 0};
#pragma unroll
    for (int oc = 0; oc < 12; oc++) {
        int4 q = sw1[oc];
        int acc = sb1[oc];
        acc = dp4a_ss((int)a16[0], q.x, acc);
        acc = dp4a_ss((int)a16[1], q.y, acc);
        acc = dp4a_ss((int)a16[2], q.z, acc);
        acc = dp4a_ss((int)a16[3], q.w, acc);
        u32 qq = requant_u8(acc, M1);
        int k = oc & 3;
        ow[oc >> 2] = (k == 0) ? qq : bins(ow[oc >> 2], qq, k);
    }
    size_t p = ibase + (size_t)(by + ty) * 512 + (bx + tx);
    u32* op = (u32*)g_bufB + p * 3;
    op[0] = ow[0]; op[1] = ow[1]; op[2] = ow[2];
}

// ---------------------------------------------------------------------------
// Layers 2-5: 3x3 conv, 12 -> 12, pad 1.  dir=0: B->A, dir=1: A->B
// 4 pixels per thread; weights streamed per-ky; outputs stored per oc-group.
// ---------------------------------------------------------------------------
__global__ __launch_bounds__(256, 3) void k_l3(int dir, const int* __restrict__ w,
                                               const int* __restrict__ b, float M) {
    const u8* in = dir ? g_bufA : g_bufB;
    u8* out = dir ? g_bufB : g_bufA;
    __shared__ __align__(16) u32 splane[3 * 10 * 132];   // 15840 B
    __shared__ __align__(16) int sww[12 * 40];           // [oc][ky][12]+bias@36
    int tx = threadIdx.x, ty = threadIdx.y;
    int tid = ty * 32 + tx;
    int bx0 = blockIdx.x * 128, by = blockIdx.y * 8, n = blockIdx.z;
    size_t ibase = (size_t)n * 262144;

    for (int i = tid; i < 12 * 40; i += 256) {
        int oc = i / 40, t = i % 40;
        int word = 0;
        if (t < 36) {
            int ky = t / 12, j = t % 12;
            if (j < 9) {
                int kx = j / 3, g = j % 3;
#pragma unroll
                for (int jj = 0; jj < 4; jj++) {
                    int ic = g * 4 + jj;
                    word |= ((w[((oc * 12 + ic) * 3 + ky) * 3 + kx] - 128) & 255) << (8 * jj);
                }
            }
        } else if (t == 36) {
            word = b[oc];
        }
        sww[i] = word;
    }

    for (int i = tid; i < 3900; i += 256) {
        int g = i / 1300, rem = i % 1300;
        int row = rem / 130, col = rem % 130;
        int gy = by - 1 + row, gx = bx0 - 1 + col;
        u32 v = 0;
        if ((unsigned)gy < 512u && (unsigned)gx < 512u)
            v = ((const u32*)in)[(ibase + (size_t)gy * 512 + gx) * 3 + g];
        splane[(g * 10 + row) * 132 + col] = v;
    }
    __syncthreads();

    int av[3][3][6];
#pragma unroll
    for (int r = 0; r < 3; r++) {
#pragma unroll
        for (int g = 0; g < 3; g++) {
            const uint4* pp = (const uint4*)&splane[((g * 10) + ty + r) * 132 + 4 * tx];
            uint4 lo = pp[0], hi = pp[1];
            av[r][g][0] = (int)lo.x; av[r][g][1] = (int)lo.y;
            av[r][g][2] = (int)lo.z; av[r][g][3] = (int)lo.w;
            av[r][g][4] = (int)hi.x; av[r][g][5] = (int)hi.y;
        }
    }

    size_t p0 = ibase + (size_t)(by + ty) * 512 + (bx0 + 4 * tx);
    u32* ob = (u32*)out + p0 * 3;

    u32 go0 = 0, go1 = 0, go2 = 0, go3 = 0;
#pragma unroll
    for (int oc = 0; oc < 12; oc++) {
        int bias = sww[oc * 40 + 36];
        int acc0 = bias, acc1 = bias, acc2 = bias, acc3 = bias;
#pragma unroll
        for (int ky = 0; ky < 3; ky++) {
            alignas(16) int wv[12];
            const int4* wp = (const int4*)&sww[oc * 40 + ky * 12];
            ((int4*)wv)[0] = wp[0];
            ((int4*)wv)[1] = wp[1];
            ((int4*)wv)[2] = wp[2];
#pragma unroll
            for (int kx = 0; kx < 3; kx++) {
#pragma unroll
                for (int g = 0; g < 3; g++) {
                    int wvx = wv[kx * 3 + g];
                    acc0 = dp4a_ss(av[ky][g][kx + 0], wvx, acc0);
                    acc1 = dp4a_ss(av[ky][g][kx + 1], wvx, acc1);
                    acc2 = dp4a_ss(av[ky][g][kx + 2], wvx, acc2);
                    acc3 = dp4a_ss(av[ky][g][kx + 3], wvx, acc3);
                }
            }
        }
        u32 q0 = requant_u8(acc0, M);
        u32 q1 = requant_u8(acc1, M);
        u32 q2 = requant_u8(acc2, M);
        u32 q3 = requant_u8(acc3, M);
        int k = oc & 3;
        if (k == 0) { go0 = q0; go1 = q1; go2 = q2; go3 = q3; }
        else {
            go0 = bins(go0, q0, k); go1 = bins(go1, q1, k);
            go2 = bins(go2, q2, k); go3 = bins(go3, q3, k);
        }
        if (k == 3) {
            int gsel = oc >> 2;
            ob[0 * 3 + gsel] = go0;
            ob[1 * 3 + gsel] = go1;
            ob[2 * 3 + gsel] = go2;
            ob[3 * 3 + gsel] = go3;
        }
    }
}

// ---------------------------------------------------------------------------
// Deconv fused with layer6 (1x1, 12->16).  in: g_bufB NHWC12, out: float.
// 2 input pixels per thread (weight LDS amortized 2x), fma.rn.f32x2 pairs,
// rolling 2-column unpack buffer.
// ---------------------------------------------------------------------------
__global__ __launch_bounds__(256, 1) void k_deconv(const int* __restrict__ w6,
                                                   const int* __restrict__ b6, float M6,
                                                   const float* __restrict__ wt,
                                                   float* __restrict__ out) {
    __shared__ __align__(16) uint4 tile[10 * 66];   // rows 10, cols 66, 16 ch
    __shared__ __align__(16) float ws[81 * 16];     // [tap][ch], *0.05 folded
    __shared__ int sw6[16][3];
    __shared__ int sb6[16];
    int tx = threadIdx.x, ty = threadIdx.y;
    int tid = ty * 32 + tx;
    int bx0 = blockIdx.x * 64, by = blockIdx.y * 8, n = blockIdx.z;
    size_t ibase = (size_t)n * 262144;

    if (tid < 16) {
        int oc = tid;
#pragma unroll
        for (int g = 0; g < 3; g++) {
            int v = 0;
#pragma unroll
            for (int j = 0; j < 4; j++)
                v |= ((w6[oc * 12 + 4 * g + j] - 128) & 255) << (8 * j);
            sw6[oc][g] = v;
        }
        sb6[oc] = b6[oc];
    }
    for (int i = tid; i < 1296; i += 256) {
        int c = i / 81, t = i % 81;
        ws[t * 16 + c] = wt[c * 81 + t] * 0.05f;
    }
    __syncthreads();

    // tile fill with fused l6 (OOB stays 0 = conv zero-padding)
    for (int i = tid; i < 660; i += 256) {
        int r = i / 66, cc = i % 66;
        int py = by - 1 + r, px = bx0 - 1 + cc;
        uint4 vv = make_uint4(0, 0, 0, 0);
        if ((unsigned)py < 512u && (unsigned)px < 512u) {
            const u32* ip = (const u32*)g_bufB + (ibase + (size_t)py * 512 + px) * 3;
            int a0 = (int)ip[0], a1 = (int)ip[1], a2 = (int)ip[2];
            u32 o[4] = {0, 0, 0, 0};
#pragma unroll
            for (int oc = 0; oc < 16; oc++) {
                int acc = sb6[oc];
                acc = dp4a_ss(a0, sw6[oc][0], acc);
                acc = dp4a_ss(a1, sw6[oc][1], acc);
                acc = dp4a_ss(a2, sw6[oc][2], acc);
                u32 q = requant_u8(acc, M6);
                int k = oc & 3;
                o[oc >> 2] = (k == 0) ? q : bins(o[oc >> 2], q, k);
            }
            vv = make_uint4(o[0], o[1], o[2], o[3]);
        }
        tile[i] = vv;
    }
    __syncthreads();

    u64 accA[16], accB[16];
#pragma unroll
    for (int k = 0; k < 16; k++) { accA[k] = 0ull; accB[k] = 0ull; }

    int p0 = 2 * tx;   // tile-local col of pixel A; pixel B = p0+1

#pragma unroll
    for (int jy = 0; jy < 3; jy++) {
        int rowb = (ty + 2 - jy) * 66 + p0;
        u64 fb[2][8];
#define UNPACK8(dst, off)                                                     \
        {                                                                     \
            uint4 pw = tile[rowb + (off)];                                    \
            u32 wd[4] = {pw.x, pw.y, pw.z, pw.w};                             \
            _Pragma("unroll")                                                 \
            for (int q = 0; q < 4; q++) {                                     \
                float f0 = (float)((wd[q]) & 255u);                           \
                float f1 = (float)((wd[q] >> 8) & 255u);                      \
                float f2 = (float)((wd[q] >> 16) & 255u);                     \
                float f3 = (float)((wd[q] >> 24) & 255u);                     \
                dst[q * 2 + 0] = pack2(f0, f1);                               \
                dst[q * 2 + 1] = pack2(f2, f3);                               \
            }                                                                 \
        }
        UNPACK8(fb[0], 2)   // col p0+2 (parity 0)
        UNPACK8(fb[1], 3)   // col p0+3 (parity 1)
        const int rycnt = (jy == 2) ? 1 : 4;
#pragma unroll
        for (int jx = 0; jx < 3; jx++) {
            const u64* fA = fb[jx & 1];
            const u64* fB = fb[(jx + 1) & 1];
            const int rxcnt = (jx == 2) ? 1 : 4;
#pragma unroll
            for (int ry = 0; ry < 4; ry++) {
                if (ry >= rycnt) break;
#pragma unroll
                for (int rx = 0; rx < 4; rx++) {
                    if (rx >= rxcnt) break;
                    const ulonglong2* wp =
                        (const ulonglong2*)&ws[((ry + 4 * jy) * 9 + (rx + 4 * jx)) * 16];
                    ulonglong2 wa = wp[0], wb = wp[1], wc = wp[2], wdd = wp[3];
                    u64 a = accA[ry * 4 + rx];
                    u64 bb = accB[ry * 4 + rx];
                    a = fma2(fA[0], wa.x, a);   bb = fma2(fB[0], wa.x, bb);
                    a = fma2(fA[1], wa.y, a);   bb = fma2(fB[1], wa.y, bb);
                    a = fma2(fA[2], wb.x, a);   bb = fma2(fB[2], wb.x, bb);
                    a = fma2(fA[3], wb.y, a);   bb = fma2(fB[3], wb.y, bb);
                    a = fma2(fA[4], wc.x, a);   bb = fma2(fB[4], wc.x, bb);
                    a = fma2(fA[5], wc.y, a);   bb = fma2(fB[5], wc.y, bb);
                    a = fma2(fA[6], wdd.x, a);  bb = fma2(fB[6], wdd.x, bb);
                    a = fma2(fA[7], wdd.y, a);  bb = fma2(fB[7], wdd.y, bb);
                    accA[ry * 4 + rx] = a;
                    accB[ry * 4 + rx] = bb;
                }
            }
            // roll: next jx needs col p0+1-jx at parity (jx&1)
            if (jx == 0) UNPACK8(fb[1], 1)        // col p0+1
            else if (jx == 1) UNPACK8(fb[0], 0)   // col p0
        }
#undef UNPACK8
    }

    int X0 = bx0 + p0;          // global input pixel of A
    int oy0 = (by + ty) * 4;
    size_t obase = (size_t)n * 2045 * 2045;
#pragma unroll
    for (int ry = 0; ry < 4; ry++) {
        int oy = oy0 + ry;
        if (oy >= 2045) continue;
        size_t rbase = obase + (size_t)oy * 2045;
#pragma unroll
        for (int rx = 0; rx < 4; rx++) {
            int oxA = 4 * X0 + rx;
            int oxB = oxA + 4;
            if (oxA < 2045) {
                float2 pr = *(float2*)&accA[ry * 4 + rx];
                out[rbase + oxA] = pr.x + pr.y;
            }
            if (oxB < 2045) {
                float2 pr = *(float2*)&accB[ry * 4 + rx];
                out[rbase + oxB] = pr.x + pr.y;
            }
        }
    }
}

// ---------------------------------------------------------------------------
extern "C" void kernel_launch(void* const* d_in, const int* in_sizes, int n_in,
                              void* d_out, int out_size) {
    const float* x = (const float*)d_in[0];
    const int* w[7];
    const int* b[7];
    if (in_sizes[2] == 16) {
        for (int i = 0; i < 7; i++) {
            w[i] = (const int*)d_in[1 + 2 * i];
            b[i] = (const int*)d_in[2 + 2 * i];
        }
    } else {
        for (int i = 0; i < 7; i++) {
            w[i] = (const int*)d_in[1 + i];
            b[i] = (const int*)d_in[8 + i];
        }
    }
    const float* wt = (const float*)d_in[15];

    float M0 = (float)((1.0 / 255.0) * 0.02 / 0.05);
    float M1 = (float)(0.05 * 0.02 / 0.04);
    float M2 = (float)(0.04 * 0.02 / 0.04);
    float M6 = (float)(0.04 * 0.02 / 0.05);

    dim3 blk(32, 8);
    dim3 grdF(16, 64, 16);     // front: 32x8 tiles
    dim3 grd3(4, 64, 16);      // k_l3: 128x8 tiles
    dim3 grdD(8, 64, 16);      // deconv: 64x8 input tiles, 2 px/thread
    k_front<<<grdF, blk>>>(x, w[0], b[0], w[1], b[1], M0, M1);
    k_l3<<<grd3, blk>>>(0, w[2], b[2], M2);   // B -> A
    k_l3<<<grd3, blk>>>(1, w[3], b[3], M2);   // A -> B
    k_l3<<<grd3, blk>>>(0, w[4], b[4], M2);   // B -> A
    k_l3<<<grd3, blk>>>(1, w[5], b[5], M2);   // A -> B
    k_deconv<<<grdD, blk>>>(w[6], b[6], M6, wt, (float*)d_out);
}

// round 8
// speedup vs baseline: 1.1432x; 1.1432x over previous
#include <cuda_runtime.h>
#include <stdint.h>

typedef unsigned int u32;
typedef unsigned long long u64;
typedef uint8_t u8;

// Ping-pong activation scratch: 16 imgs * 512*512 pixels * up to 16 ch (NHWC)
__device__ __align__(16) u8 g_bufA[(size_t)16 * 512 * 512 * 16];
__device__ __align__(16) u8 g_bufB[(size_t)16 * 512 * 512 * 16];

__device__ __forceinline__ int dp4a_us(u32 a, int b, int c) {
    int d;
    asm("dp4a.u32.s32 %0, %1, %2, %3;" : "=r"(d) : "r"(a), "r"(b), "r"(c));
    return d;
}
__device__ __forceinline__ int dp4a_ss(int a, int b, int c) {
    int d;
    asm("dp4a.s32.s32 %0, %1, %2, %3;" : "=r"(d) : "r"(a), "r"(b), "r"(c));
    return d;
}
__device__ __forceinline__ u64 fma2(u64 a, u64 b, u64 c) {
    u64 d;
    asm("fma.rn.f32x2 %0, %1, %2, %3;" : "=l"(d) : "l"(a), "l"(b), "l"(c));
    return d;
}
__device__ __forceinline__ u64 pack2(float lo, float hi) {
    u64 d;
    asm("mov.b64 %0, {%1, %2};" : "=l"(d) : "f"(lo), "f"(hi));
    return d;
}

// requant: clip(round(acc*M),-127,127) then relu == rni+sat-to-u8 after min 127
__device__ __forceinline__ u32 requant_u8(int acc, float M) {
    float f = fminf((float)acc * M, 127.0f);
    unsigned short s;
    asm("cvt.rni.sat.u8.f32 %0, %1;" : "=h"(s) : "f"(f));
    return (u32)s;
}
// insert byte q.b0 into byte lane k of go (k=1,2,3); k=0 is plain assign
__device__ __forceinline__ u32 bins(u32 go, u32 q, int k) {
    const u32 sel[4] = {0x3214u, 0x3240u, 0x3410u, 0x4210u};
    return __byte_perm(go, q, sel[k]);
}

// ---------------------------------------------------------------------------
// Front: quantize + layer0 (5x5, 1->16, pad 2) + layer1 (1x1, 16->12) fused.
// in: x float, out: g_bufB NHWC12
// ---------------------------------------------------------------------------
__global__ __launch_bounds__(256) void k_front(const float* __restrict__ x,
                                               const int* __restrict__ w0,
                                               const int* __restrict__ b0,
                                               const int* __restrict__ w1,
                                               const int* __restrict__ b1,
                                               float M0, float M1) {
    __shared__ __align__(16) u8 tile[12][36];
    __shared__ __align__(16) int4 sw[16][2];
    __shared__ int4 sw1[12];
    __shared__ int sb1[12];
    int tx = threadIdx.x, ty = threadIdx.y;
    int tid = ty * 32 + tx;
    int bx = blockIdx.x * 32, by = blockIdx.y * 8, n = blockIdx.z;
    size_t ibase = (size_t)n * 262144;
    const float inv_s = (float)(1.0 / 255.0);

    for (int i = tid; i < 432; i += 256) {
        int r = i / 36, c = i % 36;
        int gy = by - 2 + r, gx = bx - 2 + c;
        u8 v = 0;
        if ((unsigned)gy < 512u && (unsigned)gx < 512u) {
            float f = x[ibase + (size_t)gy * 512 + gx];
            v = (u8)min(max(__float2int_rn(f / inv_s), 0), 255);
        }
        tile[r][c] = v;
    }
    if (tid < 16) {
        int oc = tid;
        int rw[5];
        int cw = 0;
#pragma unroll
        for (int ky = 0; ky < 5; ky++) {
            int wv = 0;
#pragma unroll
            for (int kx = 0; kx < 4; kx++)
                wv |= ((w0[oc * 25 + ky * 5 + kx] - 128) & 255) << (8 * kx);
            rw[ky] = wv;
        }
#pragma unroll
        for (int ky = 0; ky < 4; ky++)
            cw |= ((w0[oc * 25 + ky * 5 + 4] - 128) & 255) << (8 * ky);
        int corner = w0[oc * 25 + 24] - 128;
        sw[oc][0] = make_int4(rw[0], rw[1], rw[2], rw[3]);
        sw[oc][1] = make_int4(rw[4], cw, corner, b0[oc]);
    }
    if (tid >= 32 && tid < 44) {
        int oc = tid - 32;
        int ww[4];
#pragma unroll
        for (int g = 0; g < 4; g++) {
            int v = 0;
#pragma unroll
            for (int j = 0; j < 4; j++)
                v |= ((w1[oc * 16 + 4 * g + j] - 128) & 255) << (8 * j);
            ww[g] = v;
        }
        sw1[oc] = make_int4(ww[0], ww[1], ww[2], ww[3]);
        sb1[oc] = b1[oc];
    }
    __syncthreads();

    u32 r[5], colw = 0;
    int corner_v = 0;
    int s = (tx & 3) * 8;
#pragma unroll
    for (int k = 0; k < 5; k++) {
        const u32* rowp = (const u32*)&tile[ty + k][0];
        u32 wlo = rowp[tx >> 2], whi = rowp[(tx >> 2) + 1];
        r[k] = __funnelshift_r(wlo, whi, s);
        u32 b4 = (whi >> s) & 255u;
        if (k < 4) colw |= b4 << (8 * k); else corner_v = (int)b4;
    }

    u32 a16[4] = {0, 0, 0, 0};
#pragma unroll
    for (int oc = 0; oc < 16; oc++) {
        int4 qa = sw[oc][0];
        int4 qb = sw[oc][1];
        int acc = qb.w;
        acc = dp4a_us(r[0], qa.x, acc);
        acc = dp4a_us(r[1], qa.y, acc);
        acc = dp4a_us(r[2], qa.z, acc);
        acc = dp4a_us(r[3], qa.w, acc);
        acc = dp4a_us(r[4], qb.x, acc);
        acc = dp4a_us(colw, qb.y, acc);
        acc += corner_v * qb.z;
        u32 q = requant_u8(acc, M0);
        int k = oc & 3;
        a16[oc >> 2] = (k == 0) ? q : bins(a16[oc >> 2], q, k);
    }

    u32 ow[3] = {0, 0, 0};
#pragma unroll
    for (int oc = 0; oc < 12; oc++) {
        int4 q = sw1[oc];
        int acc = sb1[oc];
        acc = dp4a_ss((int)a16[0], q.x, acc);
        acc = dp4a_ss((int)a16[1], q.y, acc);
        acc = dp4a_ss((int)a16[2], q.z, acc);
        acc = dp4a_ss((int)a16[3], q.w, acc);
        u32 qq = requant_u8(acc, M1);
        int k = oc & 3;
        ow[oc >> 2] = (k == 0) ? qq : bins(ow[oc >> 2], qq, k);
    }
    size_t p = ibase + (size_t)(by + ty) * 512 + (bx + tx);
    u32* op = (u32*)g_bufB + p * 3;
    op[0] = ow[0]; op[1] = ow[1]; op[2] = ow[2];
}

// ---------------------------------------------------------------------------
// Layers 2-5: 3x3 conv, 12 -> 12, pad 1.  dir=0: B->A, dir=1: A->B
// 4 pixels per thread; weights streamed per-ky; outputs stored per oc-group.
// ---------------------------------------------------------------------------
__global__ __launch_bounds__(256, 3) void k_l3(int dir, const int* __restrict__ w,
                                               const int* __restrict__ b, float M) {
    const u8* in = dir ? g_bufA : g_bufB;
    u8* out = dir ? g_bufB : g_bufA;
    __shared__ __align__(16) u32 splane[3 * 10 * 132];   // 15840 B
    __shared__ __align__(16) int sww[12 * 40];           // [oc][ky][12]+bias@36
    int tx = threadIdx.x, ty = threadIdx.y;
    int tid = ty * 32 + tx;
    int bx0 = blockIdx.x * 128, by = blockIdx.y * 8, n = blockIdx.z;
    size_t ibase = (size_t)n * 262144;

    for (int i = tid; i < 12 * 40; i += 256) {
        int oc = i / 40, t = i % 40;
        int word = 0;
        if (t < 36) {
            int ky = t / 12, j = t % 12;
            if (j < 9) {
                int kx = j / 3, g = j % 3;
#pragma unroll
                for (int jj = 0; jj < 4; jj++) {
                    int ic = g * 4 + jj;
                    word |= ((w[((oc * 12 + ic) * 3 + ky) * 3 + kx] - 128) & 255) << (8 * jj);
                }
            }
        } else if (t == 36) {
            word = b[oc];
        }
        sww[i] = word;
    }

    for (int i = tid; i < 3900; i += 256) {
        int g = i / 1300, rem = i % 1300;
        int row = rem / 130, col = rem % 130;
        int gy = by - 1 + row, gx = bx0 - 1 + col;
        u32 v = 0;
        if ((unsigned)gy < 512u && (unsigned)gx < 512u)
            v = ((const u32*)in)[(ibase + (size_t)gy * 512 + gx) * 3 + g];
        splane[(g * 10 + row) * 132 + col] = v;
    }
    __syncthreads();

    int av[3][3][6];
#pragma unroll
    for (int r = 0; r < 3; r++) {
#pragma unroll
        for (int g = 0; g < 3; g++) {
            const uint4* pp = (const uint4*)&splane[((g * 10) + ty + r) * 132 + 4 * tx];
            uint4 lo = pp[0], hi = pp[1];
            av[r][g][0] = (int)lo.x; av[r][g][1] = (int)lo.y;
            av[r][g][2] = (int)lo.z; av[r][g][3] = (int)lo.w;
            av[r][g][4] = (int)hi.x; av[r][g][5] = (int)hi.y;
        }
    }

    size_t p0 = ibase + (size_t)(by + ty) * 512 + (bx0 + 4 * tx);
    u32* ob = (u32*)out + p0 * 3;

    u32 go0 = 0, go1 = 0, go2 = 0, go3 = 0;
#pragma unroll
    for (int oc = 0; oc < 12; oc++) {
        int bias = sww[oc * 40 + 36];
        int acc0 = bias, acc1 = bias, acc2 = bias, acc3 = bias;
#pragma unroll
        for (int ky = 0; ky < 3; ky++) {
            alignas(16) int wv[12];
            const int4* wp = (const int4*)&sww[oc * 40 + ky * 12];
            ((int4*)wv)[0] = wp[0];
            ((int4*)wv)[1] = wp[1];
            ((int4*)wv)[2] = wp[2];
#pragma unroll
            for (int kx = 0; kx < 3; kx++) {
#pragma unroll
                for (int g = 0; g < 3; g++) {
                    int wvx = wv[kx * 3 + g];
                    acc0 = dp4a_ss(av[ky][g][kx + 0], wvx, acc0);
                    acc1 = dp4a_ss(av[ky][g][kx + 1], wvx, acc1);
                    acc2 = dp4a_ss(av[ky][g][kx + 2], wvx, acc2);
                    acc3 = dp4a_ss(av[ky][g][kx + 3], wvx, acc3);
                }
            }
        }
        u32 q0 = requant_u8(acc0, M);
        u32 q1 = requant_u8(acc1, M);
        u32 q2 = requant_u8(acc2, M);
        u32 q3 = requant_u8(acc3, M);
        int k = oc & 3;
        if (k == 0) { go0 = q0; go1 = q1; go2 = q2; go3 = q3; }
        else {
            go0 = bins(go0, q0, k); go1 = bins(go1, q1, k);
            go2 = bins(go2, q2, k); go3 = bins(go3, q3, k);
        }
        if (k == 3) {
            int gsel = oc >> 2;
            ob[0 * 3 + gsel] = go0;
            ob[1 * 3 + gsel] = go1;
            ob[2 * 3 + gsel] = go2;
            ob[3 * 3 + gsel] = go3;
        }
    }
}

// ---------------------------------------------------------------------------
// Deconv fused with layer6 (1x1, 12->16).  in: g_bufB NHWC12, out: float.
// 1 input pixel per thread (R5 known-good shape); l6 applied during halo-tile
// fill; main loop uses packed fma.rn.f32x2 (8 f32x2 per tap-cell).
// ---------------------------------------------------------------------------
__global__ __launch_bounds__(256) void k_deconv(const int* __restrict__ w6,
                                                const int* __restrict__ b6, float M6,
                                                const float* __restrict__ wt,
                                                float* __restrict__ out) {
    __shared__ __align__(16) uint4 tile[340];      // 34 x 10 pixels, 16 ch
    __shared__ __align__(16) float ws[81 * 16];    // [tap][ch], *0.05 folded
    __shared__ int sw6[16][3];
    __shared__ int sb6[16];
    int tx = threadIdx.x, ty = threadIdx.y;
    int tid = ty * 32 + tx;
    int bx = blockIdx.x * 32, by = blockIdx.y * 8, n = blockIdx.z;
    size_t ibase = (size_t)n * 262144;

    if (tid < 16) {
        int oc = tid;
#pragma unroll
        for (int g = 0; g < 3; g++) {
            int v = 0;
#pragma unroll
            for (int j = 0; j < 4; j++)
                v |= ((w6[oc * 12 + 4 * g + j] - 128) & 255) << (8 * j);
            sw6[oc][g] = v;
        }
        sb6[oc] = b6[oc];
    }
    for (int i = tid; i < 1296; i += 256) {
        int c = i / 81, t = i % 81;
        ws[t * 16 + c] = wt[c * 81 + t] * 0.05f;
    }
    __syncthreads();

    // tile fill with fused l6 (OOB stays 0 = conv zero-padding)
    for (int i = tid; i < 340; i += 256) {
        int r = i / 34, cc = i % 34;
        int py = by - 1 + r, px = bx - 1 + cc;
        uint4 vv = make_uint4(0, 0, 0, 0);
        if ((unsigned)py < 512u && (unsigned)px < 512u) {
            const u32* ip = (const u32*)g_bufB + (ibase + (size_t)py * 512 + px) * 3;
            int a0 = (int)ip[0], a1 = (int)ip[1], a2 = (int)ip[2];
            u32 o[4] = {0, 0, 0, 0};
#pragma unroll
            for (int oc = 0; oc < 16; oc++) {
                int acc = sb6[oc];
                acc = dp4a_ss(a0, sw6[oc][0], acc);
                acc = dp4a_ss(a1, sw6[oc][1], acc);
                acc = dp4a_ss(a2, sw6[oc][2], acc);
                u32 q = requant_u8(acc, M6);
                int k = oc & 3;
                o[oc >> 2] = (k == 0) ? q : bins(o[oc >> 2], q, k);
            }
            vv = make_uint4(o[0], o[1], o[2], o[3]);
        }
        tile[i] = vv;
    }
    __syncthreads();

    u64 acc2[16];
#pragma unroll
    for (int k = 0; k < 16; k++) acc2[k] = 0ull;

#pragma unroll
    for (int jy = 0; jy < 3; jy++) {
#pragma unroll
        for (int jx = 0; jx < 3; jx++) {
            uint4 pw = tile[(ty + 2 - jy) * 34 + (tx + 2 - jx)];
            u32 wd[4] = {pw.x, pw.y, pw.z, pw.w};
            u64 v2[8];
#pragma unroll
            for (int q = 0; q < 4; q++) {
                float f0 = (float)(int)(wd[q] & 255u);
                float f1 = (float)(int)((wd[q] >> 8) & 255u);
                float f2 = (float)(int)((wd[q] >> 16) & 255u);
                float f3 = (float)(int)((wd[q] >> 24) & 255u);
                v2[q * 2 + 0] = pack2(f0, f1);
                v2[q * 2 + 1] = pack2(f2, f3);
            }
            const int rycnt = (jy == 2) ? 1 : 4;
            const int rxcnt = (jx == 2) ? 1 : 4;
#pragma unroll
            for (int ry = 0; ry < 4; ry++) {
                if (ry >= rycnt) break;
#pragma unroll
                for (int rx = 0; rx < 4; rx++) {
                    if (rx >= rxcnt) break;
                    const ulonglong2* wp =
                        (const ulonglong2*)&ws[((ry + 4 * jy) * 9 + (rx + 4 * jx)) * 16];
                    ulonglong2 wa = wp[0], wb = wp[1], wc = wp[2], wdd = wp[3];
                    u64 a = acc2[ry * 4 + rx];
                    a = fma2(v2[0], wa.x, a);
                    a = fma2(v2[1], wa.y, a);
                    a = fma2(v2[2], wb.x, a);
                    a = fma2(v2[3], wb.y, a);
                    a = fma2(v2[4], wc.x, a);
                    a = fma2(v2[5], wc.y, a);
                    a = fma2(v2[6], wdd.x, a);
                    a = fma2(v2[7], wdd.y, a);
                    acc2[ry * 4 + rx] = a;
                }
            }
        }
    }

    int oy0 = (by + ty) * 4, ox0 = (bx + tx) * 4;
    size_t obase = (size_t)n * 2045 * 2045;
#pragma unroll
    for (int ry = 0; ry < 4; ry++) {
        int oy = oy0 + ry;
        if (oy >= 2045) continue;
        size_t rbase = obase + (size_t)oy * 2045;
#pragma unroll
        for (int rx = 0; rx < 4; rx++) {
            int ox = ox0 + rx;
            if (ox < 2045) {
                float2 pr = *(float2*)&acc2[ry * 4 + rx];
                out[rbase + ox] = pr.x + pr.y;
            }
        }
    }
}

// ---------------------------------------------------------------------------
extern "C" void kernel_launch(void* const* d_in, const int* in_sizes, int n_in,
                              void* d_out, int out_size) {
    const float* x = (const float*)d_in[0];
    const int* w[7];
    const int* b[7];
    if (in_sizes[2] == 16) {
        for (int i = 0; i < 7; i++) {
            w[i] = (const int*)d_in[1 + 2 * i];
            b[i] = (const int*)d_in[2 + 2 * i];
        }
    } else {
        for (int i = 0; i < 7; i++) {
            w[i] = (const int*)d_in[1 + i];
            b[i] = (const int*)d_in[8 + i];
        }
    }
    const float* wt = (const float*)d_in[15];

    float M0 = (float)((1.0 / 255.0) * 0.02 / 0.05);
    float M1 = (float)(0.05 * 0.02 / 0.04);
    float M2 = (float)(0.04 * 0.02 / 0.04);
    float M6 = (float)(0.04 * 0.02 / 0.05);

    dim3 blk(32, 8);
    dim3 grdF(16, 64, 16);     // front: 32x8 tiles
    dim3 grd3(4, 64, 16);      // k_l3: 128x8 tiles
    dim3 grdD(16, 64, 16);     // deconv: 32x8 input tiles, 1 px/thread
    k_front<<<grdF, blk>>>(x, w[0], b[0], w[1], b[1], M0, M1);
    k_l3<<<grd3, blk>>>(0, w[2], b[2], M2);   // B -> A
    k_l3<<<grd3, blk>>>(1, w[3], b[3], M2);   // A -> B
    k_l3<<<grd3, blk>>>(0, w[4], b[4], M2);   // B -> A
    k_l3<<<grd3, blk>>>(1, w[5], b[5], M2);   // A -> B
    k_deconv<<<grdD, blk>>>(w[6], b[6], M6, wt, (float*)d_out);
}

// round 9
// speedup vs baseline: 1.3160x; 1.1511x over previous
#include <cuda_runtime.h>
#include <stdint.h>

typedef unsigned int u32;
typedef unsigned long long u64;
typedef uint8_t u8;

// Ping-pong activation scratch: 16 imgs * 512*512 pixels * up to 16 ch (NHWC)
__device__ __align__(16) u8 g_bufA[(size_t)16 * 512 * 512 * 16];
__device__ __align__(16) u8 g_bufB[(size_t)16 * 512 * 512 * 16];
// Two-level quantized deconv weights: per tap (81), 4 words = 16 ch bytes
__device__ __align__(16) int g_wq[81 * 4];
__device__ __align__(16) int g_wr[81 * 4];
__device__ float g_sc[2];   // [0] = s*0.05, [1] = s*0.05/256

__device__ __forceinline__ int dp4a_us(u32 a, int b, int c) {
    int d;
    asm("dp4a.u32.s32 %0, %1, %2, %3;" : "=r"(d) : "r"(a), "r"(b), "r"(c));
    return d;
}
__device__ __forceinline__ int dp4a_ss(int a, int b, int c) {
    int d;
    asm("dp4a.s32.s32 %0, %1, %2, %3;" : "=r"(d) : "r"(a), "r"(b), "r"(c));
    return d;
}

// requant: clip(round(acc*M),-127,127) then relu == rni+sat-to-u8 after min 127
__device__ __forceinline__ u32 requant_u8(int acc, float M) {
    float f = fminf((float)acc * M, 127.0f);
    unsigned short s;
    asm("cvt.rni.sat.u8.f32 %0, %1;" : "=h"(s) : "f"(f));
    return (u32)s;
}
// insert byte q.b0 into byte lane k of go (k=1,2,3); k=0 is plain assign
__device__ __forceinline__ u32 bins(u32 go, u32 q, int k) {
    const u32 sel[4] = {0x3214u, 0x3240u, 0x3410u, 0x4210u};
    return __byte_perm(go, q, sel[k]);
}

// ---------------------------------------------------------------------------
// Prep: two-level int8 quantization of the deconv weight.
// w = s*(q + r/256), s = max|w|/127.  Deterministic, 1 block.
// ---------------------------------------------------------------------------
__global__ __launch_bounds__(256) void k_prep(const float* __restrict__ wt) {
    __shared__ float red[256];
    int tid = threadIdx.x;
    float m = 0.0f;
    for (int i = tid; i < 1296; i += 256) m = fmaxf(m, fabsf(wt[i]));
    red[tid] = m;
    __syncthreads();
    for (int s = 128; s > 0; s >>= 1) {
        if (tid < s) red[tid] = fmaxf(red[tid], red[tid + s]);
        __syncthreads();
    }
    float mx = fmaxf(red[0], 1e-20f);
    float s = mx / 127.0f;
    float inv_s = 127.0f / mx;
    if (tid == 0) {
        g_sc[0] = s * 0.05f;
        g_sc[1] = s * 0.05f / 256.0f;
    }
    for (int i = tid; i < 324; i += 256) {
        int t = i >> 2, g = i & 3;
        u32 qw = 0, rw = 0;
#pragma unroll
        for (int j = 0; j < 4; j++) {
            float w = wt[(g * 4 + j) * 81 + t];
            int q = __float2int_rn(w * inv_s);
            q = min(max(q, -127), 127);
            float rem = w - s * (float)q;
            int r = __float2int_rn(rem * inv_s * 256.0f);
            r = min(max(r, -127), 127);
            qw |= ((u32)q & 255u) << (8 * j);
            rw |= ((u32)r & 255u) << (8 * j);
        }
        g_wq[t * 4 + g] = (int)qw;
        g_wr[t * 4 + g] = (int)rw;
    }
}

// ---------------------------------------------------------------------------
// Front: quantize + layer0 (5x5, 1->16, pad 2) + layer1 (1x1, 16->12) fused.
// in: x float, out: g_bufB NHWC12
// ---------------------------------------------------------------------------
__global__ __launch_bounds__(256) void k_front(const float* __restrict__ x,
                                               const int* __restrict__ w0,
                                               const int* __restrict__ b0,
                                               const int* __restrict__ w1,
                                               const int* __restrict__ b1,
                                               float M0, float M1) {
    __shared__ __align__(16) u8 tile[12][36];
    __shared__ __align__(16) int4 sw[16][2];
    __shared__ int4 sw1[12];
    __shared__ int sb1[12];
    int tx = threadIdx.x, ty = threadIdx.y;
    int tid = ty * 32 + tx;
    int bx = blockIdx.x * 32, by = blockIdx.y * 8, n = blockIdx.z;
    size_t ibase = (size_t)n * 262144;
    const float inv_s = (float)(1.0 / 255.0);

    for (int i = tid; i < 432; i += 256) {
        int r = i / 36, c = i % 36;
        int gy = by - 2 + r, gx = bx - 2 + c;
        u8 v = 0;
        if ((unsigned)gy < 512u && (unsigned)gx < 512u) {
            float f = x[ibase + (size_t)gy * 512 + gx];
            v = (u8)min(max(__float2int_rn(f / inv_s), 0), 255);
        }
        tile[r][c] = v;
    }
    if (tid < 16) {
        int oc = tid;
        int rw[5];
        int cw = 0;
#pragma unroll
        for (int ky = 0; ky < 5; ky++) {
            int wv = 0;
#pragma unroll
            for (int kx = 0; kx < 4; kx++)
                wv |= ((w0[oc * 25 + ky * 5 + kx] - 128) & 255) << (8 * kx);
            rw[ky] = wv;
        }
#pragma unroll
        for (int ky = 0; ky < 4; ky++)
            cw |= ((w0[oc * 25 + ky * 5 + 4] - 128) & 255) << (8 * ky);
        int corner = w0[oc * 25 + 24] - 128;
        sw[oc][0] = make_int4(rw[0], rw[1], rw[2], rw[3]);
        sw[oc][1] = make_int4(rw[4], cw, corner, b0[oc]);
    }
    if (tid >= 32 && tid < 44) {
        int oc = tid - 32;
        int ww[4];
#pragma unroll
        for (int g = 0; g < 4; g++) {
            int v = 0;
#pragma unroll
            for (int j = 0; j < 4; j++)
                v |= ((w1[oc * 16 + 4 * g + j] - 128) & 255) << (8 * j);
            ww[g] = v;
        }
        sw1[oc] = make_int4(ww[0], ww[1], ww[2], ww[3]);
        sb1[oc] = b1[oc];
    }
    __syncthreads();

    u32 r[5], colw = 0;
    int corner_v = 0;
    int s = (tx & 3) * 8;
#pragma unroll
    for (int k = 0; k < 5; k++) {
        const u32* rowp = (const u32*)&tile[ty + k][0];
        u32 wlo = rowp[tx >> 2], whi = rowp[(tx >> 2) + 1];
        r[k] = __funnelshift_r(wlo, whi, s);
        u32 b4 = (whi >> s) & 255u;
        if (k < 4) colw |= b4 << (8 * k); else corner_v = (int)b4;
    }

    u32 a16[4] = {0, 0, 0, 0};
#pragma unroll
    for (int oc = 0; oc < 16; oc++) {
        int4 qa = sw[oc][0];
        int4 qb = sw[oc][1];
        int acc = qb.w;
        acc = dp4a_us(r[0], qa.x, acc);
        acc = dp4a_us(r[1], qa.y, acc);
        acc = dp4a_us(r[2], qa.z, acc);
        acc = dp4a_us(r[3], qa.w, acc);
        acc = dp4a_us(r[4], qb.x, acc);
        acc = dp4a_us(colw, qb.y, acc);
        acc += corner_v * qb.z;
        u32 q = requant_u8(acc, M0);
        int k = oc & 3;
        a16[oc >> 2] = (k == 0) ? q : bins(a16[oc >> 2], q, k);
    }

    u32 ow[3] = {0, 0, 0};
#pragma unroll
    for (int oc = 0; oc < 12; oc++) {
        int4 q = sw1[oc];
        int acc = sb1[oc];
        acc = dp4a_ss((int)a16[0], q.x, acc);
        acc = dp4a_ss((int)a16[1], q.y, acc);
        acc = dp4a_ss((int)a16[2], q.z, acc);
        acc = dp4a_ss((int)a16[3], q.w, acc);
        u32 qq = requant_u8(acc, M1);
        int k = oc & 3;
        ow[oc >> 2] = (k == 0) ? qq : bins(ow[oc >> 2], qq, k);
    }
    size_t p = ibase + (size_t)(by + ty) * 512 + (bx + tx);
    u32* op = (u32*)g_bufB + p * 3;
    op[0] = ow[0]; op[1] = ow[1]; op[2] = ow[2];
}

// ---------------------------------------------------------------------------
// Layers 2-5: 3x3 conv, 12 -> 12, pad 1.  dir=0: B->A, dir=1: A->B
// 4 pixels per thread; weights streamed per-ky; outputs stored per oc-group.
// ---------------------------------------------------------------------------
__global__ __launch_bounds__(256, 3) void k_l3(int dir, const int* __restrict__ w,
                                               const int* __restrict__ b, float M) {
    const u8* in = dir ? g_bufA : g_bufB;
    u8* out = dir ? g_bufB : g_bufA;
    __shared__ __align__(16) u32 splane[3 * 10 * 132];   // 15840 B
    __shared__ __align__(16) int sww[12 * 40];           // [oc][ky][12]+bias@36
    int tx = threadIdx.x, ty = threadIdx.y;
    int tid = ty * 32 + tx;
    int bx0 = blockIdx.x * 128, by = blockIdx.y * 8, n = blockIdx.z;
    size_t ibase = (size_t)n * 262144;

    for (int i = tid; i < 12 * 40; i += 256) {
        int oc = i / 40, t = i % 40;
        int word = 0;
        if (t < 36) {
            int ky = t / 12, j = t % 12;
            if (j < 9) {
                int kx = j / 3, g = j % 3;
#pragma unroll
                for (int jj = 0; jj < 4; jj++) {
                    int ic = g * 4 + jj;
                    word |= ((w[((oc * 12 + ic) * 3 + ky) * 3 + kx] - 128) & 255) << (8 * jj);
                }
            }
        } else if (t == 36) {
            word = b[oc];
        }
        sww[i] = word;
    }

    for (int i = tid; i < 3900; i += 256) {
        int g = i / 1300, rem = i % 1300;
        int row = rem / 130, col = rem % 130;
        int gy = by - 1 + row, gx = bx0 - 1 + col;
        u32 v = 0;
        if ((unsigned)gy < 512u && (unsigned)gx < 512u)
            v = ((const u32*)in)[(ibase + (size_t)gy * 512 + gx) * 3 + g];
        splane[(g * 10 + row) * 132 + col] = v;
    }
    __syncthreads();

    int av[3][3][6];
#pragma unroll
    for (int r = 0; r < 3; r++) {
#pragma unroll
        for (int g = 0; g < 3; g++) {
            const uint4* pp = (const uint4*)&splane[((g * 10) + ty + r) * 132 + 4 * tx];
            uint4 lo = pp[0], hi = pp[1];
            av[r][g][0] = (int)lo.x; av[r][g][1] = (int)lo.y;
            av[r][g][2] = (int)lo.z; av[r][g][3] = (int)lo.w;
            av[r][g][4] = (int)hi.x; av[r][g][5] = (int)hi.y;
        }
    }

    size_t p0 = ibase + (size_t)(by + ty) * 512 + (bx0 + 4 * tx);
    u32* ob = (u32*)out + p0 * 3;

    u32 go0 = 0, go1 = 0, go2 = 0, go3 = 0;
#pragma unroll
    for (int oc = 0; oc < 12; oc++) {
        int bias = sww[oc * 40 + 36];
        int acc0 = bias, acc1 = bias, acc2 = bias, acc3 = bias;
#pragma unroll
        for (int ky = 0; ky < 3; ky++) {
            alignas(16) int wv[12];
            const int4* wp = (const int4*)&sww[oc * 40 + ky * 12];
            ((int4*)wv)[0] = wp[0];
            ((int4*)wv)[1] = wp[1];
            ((int4*)wv)[2] = wp[2];
#pragma unroll
            for (int kx = 0; kx < 3; kx++) {
#pragma unroll
                for (int g = 0; g < 3; g++) {
                    int wvx = wv[kx * 3 + g];
                    acc0 = dp4a_ss(av[ky][g][kx + 0], wvx, acc0);
                    acc1 = dp4a_ss(av[ky][g][kx + 1], wvx, acc1);
                    acc2 = dp4a_ss(av[ky][g][kx + 2], wvx, acc2);
                    acc3 = dp4a_ss(av[ky][g][kx + 3], wvx, acc3);
                }
            }
        }
        u32 q0 = requant_u8(acc0, M);
        u32 q1 = requant_u8(acc1, M);
        u32 q2 = requant_u8(acc2, M);
        u32 q3 = requant_u8(acc3, M);
        int k = oc & 3;
        if (k == 0) { go0 = q0; go1 = q1; go2 = q2; go3 = q3; }
        else {
            go0 = bins(go0, q0, k); go1 = bins(go1, q1, k);
            go2 = bins(go2, q2, k); go3 = bins(go3, q3, k);
        }
        if (k == 3) {
            int gsel = oc >> 2;
            ob[0 * 3 + gsel] = go0;
            ob[1 * 3 + gsel] = go1;
            ob[2 * 3 + gsel] = go2;
            ob[3 * 3 + gsel] = go3;
        }
    }
}

// ---------------------------------------------------------------------------
// Deconv fused with layer6 (1x1, 12->16).  in: g_bufB NHWC12, out: float.
// All-integer main loop: two-level int8 weights (q + r/256), dp4a directly on
// packed u8 tile words (no unpack), 2 LDS.128 weights per tap-cell.
// ---------------------------------------------------------------------------
__global__ __launch_bounds__(256) void k_deconv(const int* __restrict__ w6,
                                                const int* __restrict__ b6, float M6,
                                                float* __restrict__ out) {
    __shared__ __align__(16) uint4 tile[340];      // 34 x 10 pixels, 16 ch
    __shared__ __align__(16) int swq[81 * 4];      // q words per tap
    __shared__ __align__(16) int swr[81 * 4];      // r words per tap
    __shared__ int sw6[16][3];
    __shared__ int sb6[16];
    int tx = threadIdx.x, ty = threadIdx.y;
    int tid = ty * 32 + tx;
    int bx = blockIdx.x * 32, by = blockIdx.y * 8, n = blockIdx.z;
    size_t ibase = (size_t)n * 262144;

    if (tid < 16) {
        int oc = tid;
#pragma unroll
        for (int g = 0; g < 3; g++) {
            int v = 0;
#pragma unroll
            for (int j = 0; j < 4; j++)
                v |= ((w6[oc * 12 + 4 * g + j] - 128) & 255) << (8 * j);
            sw6[oc][g] = v;
        }
        sb6[oc] = b6[oc];
    }
    for (int i = tid; i < 324; i += 256) {
        swq[i] = g_wq[i];
        swr[i] = g_wr[i];
    }
    float sq = g_sc[0], sr = g_sc[1];
    __syncthreads();

    // tile fill with fused l6 (OOB stays 0 = conv zero-padding)
    for (int i = tid; i < 340; i += 256) {
        int r = i / 34, cc = i % 34;
        int py = by - 1 + r, px = bx - 1 + cc;
        uint4 vv = make_uint4(0, 0, 0, 0);
        if ((unsigned)py < 512u && (unsigned)px < 512u) {
            const u32* ip = (const u32*)g_bufB + (ibase + (size_t)py * 512 + px) * 3;
            int a0 = (int)ip[0], a1 = (int)ip[1], a2 = (int)ip[2];
            u32 o[4] = {0, 0, 0, 0};
#pragma unroll
            for (int oc = 0; oc < 16; oc++) {
                int acc = sb6[oc];
                acc = dp4a_ss(a0, sw6[oc][0], acc);
                acc = dp4a_ss(a1, sw6[oc][1], acc);
                acc = dp4a_ss(a2, sw6[oc][2], acc);
                u32 q = requant_u8(acc, M6);
                int k = oc & 3;
                o[oc >> 2] = (k == 0) ? q : bins(o[oc >> 2], q, k);
            }
            vv = make_uint4(o[0], o[1], o[2], o[3]);
        }
        tile[i] = vv;
    }
    __syncthreads();

    int accQ[16], accR[16];
#pragma unroll
    for (int k = 0; k < 16; k++) { accQ[k] = 0; accR[k] = 0; }

#pragma unroll
    for (int jy = 0; jy < 3; jy++) {
#pragma unroll
        for (int jx = 0; jx < 3; jx++) {
            uint4 pw = tile[(ty + 2 - jy) * 34 + (tx + 2 - jx)];
            u32 w0 = pw.x, w1 = pw.y, w2 = pw.z, w3 = pw.w;
            const int rycnt = (jy == 2) ? 1 : 4;
            const int rxcnt = (jx == 2) ? 1 : 4;
#pragma unroll
            for (int ry = 0; ry < 4; ry++) {
                if (ry >= rycnt) break;
#pragma unroll
                for (int rx = 0; rx < 4; rx++) {
                    if (rx >= rxcnt) break;
                    int tap = (ry + 4 * jy) * 9 + (rx + 4 * jx);
                    int4 q4 = ((const int4*)swq)[tap];
                    int4 r4 = ((const int4*)swr)[tap];
                    int aq = accQ[ry * 4 + rx];
                    aq = dp4a_us(w0, q4.x, aq);
                    aq = dp4a_us(w1, q4.y, aq);
                    aq = dp4a_us(w2, q4.z, aq);
                    aq = dp4a_us(w3, q4.w, aq);
                    accQ[ry * 4 + rx] = aq;
                    int ar = accR[ry * 4 + rx];
                    ar = dp4a_us(w0, r4.x, ar);
                    ar = dp4a_us(w1, r4.y, ar);
                    ar = dp4a_us(w2, r4.z, ar);
                    ar = dp4a_us(w3, r4.w, ar);
                    accR[ry * 4 + rx] = ar;
                }
            }
        }
    }

    int oy0 = (by + ty) * 4, ox0 = (bx + tx) * 4;
    size_t obase = (size_t)n * 2045 * 2045;
#pragma unroll
    for (int ry = 0; ry < 4; ry++) {
        int oy = oy0 + ry;
        if (oy >= 2045) continue;
        size_t rbase = obase + (size_t)oy * 2045;
#pragma unroll
        for (int rx = 0; rx < 4; rx++) {
            int ox = ox0 + rx;
            if (ox < 2045) {
                int c = ry * 4 + rx;
                out[rbase + ox] = fmaf(sq, (float)accQ[c], sr * (float)accR[c]);
            }
        }
    }
}

// ---------------------------------------------------------------------------
extern "C" void kernel_launch(void* const* d_in, const int* in_sizes, int n_in,
                              void* d_out, int out_size) {
    const float* x = (const float*)d_in[0];
    const int* w[7];
    const int* b[7];
    if (in_sizes[2] == 16) {
        for (int i = 0; i < 7; i++) {
            w[i] = (const int*)d_in[1 + 2 * i];
            b[i] = (const int*)d_in[2 + 2 * i];
        }
    } else {
        for (int i = 0; i < 7; i++) {
            w[i] = (const int*)d_in[1 + i];
            b[i] = (const int*)d_in[8 + i];
        }
    }
    const float* wt = (const float*)d_in[15];

    float M0 = (float)((1.0 / 255.0) * 0.02 / 0.05);
    float M1 = (float)(0.05 * 0.02 / 0.04);
    float M2 = (float)(0.04 * 0.02 / 0.04);
    float M6 = (float)(0.04 * 0.02 / 0.05);

    dim3 blk(32, 8);
    dim3 grdF(16, 64, 16);     // front: 32x8 tiles
    dim3 grd3(4, 64, 16);      // k_l3: 128x8 tiles
    dim3 grdD(16, 64, 16);     // deconv: 32x8 input tiles, 1 px/thread
    k_prep<<<1, 256>>>(wt);
    k_front<<<grdF, blk>>>(x, w[0], b[0], w[1], b[1], M0, M1);
    k_l3<<<grd3, blk>>>(0, w[2], b[2], M2);   // B -> A
    k_l3<<<grd3, blk>>>(1, w[3], b[3], M2);   // A -> B
    k_l3<<<grd3, blk>>>(0, w[4], b[4], M2);   // B -> A
    k_l3<<<grd3, blk>>>(1, w[5], b[5], M2);   // A -> B
    k_deconv<<<grdD, blk>>>(w[6], b[6], M6, (float*)d_out);
}